// round 7
// baseline (speedup 1.0000x reference)
#include <cuda_runtime.h>

#define NROWS   32768
#define DCOLS   2048
#define C4TOT   (DCOLS / 4)            // 512 float4 columns
#define SLABC4  64                     // float4 cols per slab = 256 scalar cols = 32 MB
#define NSLABS  (C4TOT / SLABC4)       // 8
#define SCOLS   (SLABC4 * 4)           // 256 scalar columns per slab
#define EPS     1e-6f

#define GBLK    1024                   // uniform blocks per stage
#define RPB     (NROWS / GBLK)         // 32 rows owned per block
#define ITER    (RPB / 4)              // 8 rows per thread (4 row-workers)

// Allocation-free scratch; all state returns to zero each launch sequence.
__device__ float g_u[DCOLS];
__device__ float g_s[DCOLS];
__device__ int   g_cnt[DCOLS];

// ---------------------------------------------------------------------------
// One pipeline stage; EVERY block does both roles on its 32-row stripe:
//   B: y = x * s for slab bslab  (ldcs reads -> L2 hits, stcs writes)
//   A: sum-of-squares for slab aslab (default loads -> allocate slab in L2)
// Homogeneous blocks -> no role tail; read+write DRAM streams overlap.
__global__ void __launch_bounds__(256)
stage_kernel(const float4* __restrict__ x, float4* __restrict__ y,
             int aslab, int bslab) {
    const int tid = threadIdx.x;
    const int c4l = tid & (SLABC4 - 1);            // 0..63 float4 col in slab
    const int rw  = tid >> 6;                      // 0..3 row-worker
    const int r0  = blockIdx.x * RPB + rw;         // first row, stride 4

    // ================= B role: scale slab bslab =================
    if (bslab >= 0) {
        const size_t boff = (size_t)bslab * SLABC4 + c4l;
        const float4 s = ((const float4*)g_s)[bslab * SLABC4 + c4l];
        const size_t base = (size_t)r0 * C4TOT + boff;
#pragma unroll
        for (int r = 0; r < ITER; ++r) {
            const size_t o = base + (size_t)(r * 4) * C4TOT;
            float4 v = __ldcs(x + o);
            v.x *= s.x; v.y *= s.y; v.z *= s.z; v.w *= s.w;
            __stcs(y + o, v);
        }
    }

    // ================= A role: reduce slab aslab =================
    if (aslab >= 0) {
        const size_t aoff = (size_t)aslab * SLABC4 + c4l;
        const float4* __restrict__ xa = x + (size_t)r0 * C4TOT + aoff;

        float ax = 0.f, ay = 0.f, az = 0.f, aw = 0.f;
#pragma unroll
        for (int r = 0; r < ITER; ++r) {
            float4 v = xa[(size_t)(r * 4) * C4TOT];
            ax = fmaf(v.x, v.x, ax); ay = fmaf(v.y, v.y, ay);
            az = fmaf(v.z, v.z, az); aw = fmaf(v.w, v.w, aw);
        }

        // combine the 4 row-workers per column in shared (unique slots)
        __shared__ float sacc[4][SCOLS];
        sacc[rw][c4l * 4 + 0] = ax;
        sacc[rw][c4l * 4 + 1] = ay;
        sacc[rw][c4l * 4 + 2] = az;
        sacc[rw][c4l * 4 + 3] = aw;
        __syncthreads();

        const int scol = aslab * SCOLS + tid;      // global scalar column
        float v = sacc[0][tid] + sacc[1][tid] + sacc[2][tid] + sacc[3][tid];
        atomicAdd(&g_u[scol], v);
        __threadfence();                           // publish before counting
        if (atomicAdd(&g_cnt[scol], 1) == GBLK - 1) {
            float tot = atomicExch(&g_u[scol], 0.0f);  // complete sum + reset
            g_s[scol]   = rsqrtf(tot + EPS);
            g_cnt[scol] = 0;                       // reset for next replay
        }
    }
}

// ---------------------------------------------------------------------------
extern "C" void kernel_launch(void* const* d_in, const int* in_sizes, int n_in,
                              void* d_out, int out_size) {
    const float4* x = (const float4*)d_in[0];
    float4*       y = (float4*)d_out;

    // Software pipeline: stage s reduces slab s while scaling slab s-1.
    for (int s = 0; s <= NSLABS; ++s) {
        int aslab = (s < NSLABS) ? s : -1;
        int bslab = (s > 0) ? s - 1 : -1;
        stage_kernel<<<GBLK, 256>>>(x, y, aslab, bslab);
    }
}

// round 8
// speedup vs baseline: 1.5160x; 1.5160x over previous
#include <cuda_runtime.h>

#define NROWS   32768
#define DCOLS   2048
#define C4TOT   (DCOLS / 4)          // 512 float4 columns per row
#define SLABC4  128                  // float4 cols per slab = 512 scalar cols = 64 MB
#define NSLABS  (C4TOT / SLABC4)     // 4
#define EPS     1e-6f

// Allocation-free scratch (__device__ globals). Returned to zero by the
// kernels themselves, so graph replays see identical initial state.
__device__ float g_u[DCOLS];         // column sum-of-squares accumulators
__device__ float g_s[DCOLS];         // rsqrt scales
__device__ int   g_cnt[DCOLS];       // per-column arrival counters

// ---------------------------------------------------------------------------
// Phase A: reduce one 64MB slab. Grid = G blocks x 512 threads. (Measured at
// ~6.4 TB/s in round 5 — at roofline; unchanged.)
__global__ void __launch_bounds__(512)
reduceA_kernel(const float4* __restrict__ x, int slab, int G) {
    const int tid = threadIdx.x;
    const int c4l = tid & (SLABC4 - 1);             // 0..127
    const int w   = (blockIdx.x << 2) + (tid >> 7); // row worker id
    const int W   = G << 2;                         // total row workers
    const size_t coff = (size_t)slab * SLABC4 + c4l;

    float ax = 0.f, ay = 0.f, az = 0.f, aw = 0.f;
    int r = w;
    for (; r + 3 * W < NROWS; r += 4 * W) {
        float4 v0 = x[(size_t)(r        ) * C4TOT + coff];
        float4 v1 = x[(size_t)(r +     W) * C4TOT + coff];
        float4 v2 = x[(size_t)(r + 2 * W) * C4TOT + coff];
        float4 v3 = x[(size_t)(r + 3 * W) * C4TOT + coff];
        ax = fmaf(v0.x, v0.x, ax); ay = fmaf(v0.y, v0.y, ay);
        az = fmaf(v0.z, v0.z, az); aw = fmaf(v0.w, v0.w, aw);
        ax = fmaf(v1.x, v1.x, ax); ay = fmaf(v1.y, v1.y, ay);
        az = fmaf(v1.z, v1.z, az); aw = fmaf(v1.w, v1.w, aw);
        ax = fmaf(v2.x, v2.x, ax); ay = fmaf(v2.y, v2.y, ay);
        az = fmaf(v2.z, v2.z, az); aw = fmaf(v2.w, v2.w, aw);
        ax = fmaf(v3.x, v3.x, ax); ay = fmaf(v3.y, v3.y, ay);
        az = fmaf(v3.z, v3.z, az); aw = fmaf(v3.w, v3.w, aw);
    }
    for (; r < NROWS; r += W) {
        float4 v = x[(size_t)r * C4TOT + coff];
        ax = fmaf(v.x, v.x, ax); ay = fmaf(v.y, v.y, ay);
        az = fmaf(v.z, v.z, az); aw = fmaf(v.w, v.w, aw);
    }

    __shared__ float sacc[4][SLABC4 * 4];
    const int rw = tid >> 7;
    sacc[rw][c4l * 4 + 0] = ax;
    sacc[rw][c4l * 4 + 1] = ay;
    sacc[rw][c4l * 4 + 2] = az;
    sacc[rw][c4l * 4 + 3] = aw;
    __syncthreads();

    const int scol = slab * (SLABC4 * 4) + tid;     // global scalar column
    float v = sacc[0][tid] + sacc[1][tid] + sacc[2][tid] + sacc[3][tid];
    atomicAdd(&g_u[scol], v);
    __threadfence();                                 // publish before counting
    if (atomicAdd(&g_cnt[scol], 1) == G - 1) {       // everyone has published
        float total = atomicExch(&g_u[scol], 0.0f);  // complete sum + reset
        g_s[scol]   = rsqrtf(total + EPS);
        g_cnt[scol] = 0;                             // reset for next replay
    }
}

// ---------------------------------------------------------------------------
// Phase B: stream one slab with explicit MLP=4. Each thread owns one float4
// column position in 4 row-quarters: 4 independent ldcs issued back-to-back,
// then the multiplies, then 4 stcs. Reads hit L2 (slab allocated by phase A);
// evict-first policy frees lines for the next slab.
__global__ void __launch_bounds__(256)
scaleB_kernel(const float4* __restrict__ x, float4* __restrict__ y, int slab) {
    const unsigned j   = blockIdx.x * 256 + threadIdx.x;  // 0..2^20-1
    const int      c4l = j & (SLABC4 - 1);                // 0..127
    const unsigned rq  = j >> 7;                          // 0..8191 (row in quarter)
    const size_t base  = (size_t)rq * C4TOT + (size_t)slab * SLABC4 + c4l;
    const size_t step  = (size_t)(NROWS / 4) * C4TOT;     // 8192-row stride

    const float4 s = ((const float4*)g_s)[slab * SLABC4 + c4l];

    float4 v0 = __ldcs(x + base);
    float4 v1 = __ldcs(x + base +     step);
    float4 v2 = __ldcs(x + base + 2 * step);
    float4 v3 = __ldcs(x + base + 3 * step);
    v0.x *= s.x; v0.y *= s.y; v0.z *= s.z; v0.w *= s.w;
    v1.x *= s.x; v1.y *= s.y; v1.z *= s.z; v1.w *= s.w;
    v2.x *= s.x; v2.y *= s.y; v2.z *= s.z; v2.w *= s.w;
    v3.x *= s.x; v3.y *= s.y; v3.z *= s.z; v3.w *= s.w;
    __stcs(y + base,            v0);
    __stcs(y + base +     step, v1);
    __stcs(y + base + 2 * step, v2);
    __stcs(y + base + 3 * step, v3);
}

// ---------------------------------------------------------------------------
extern "C" void kernel_launch(void* const* d_in, const int* in_sizes, int n_in,
                              void* d_out, int out_size) {
    const float4* x = (const float4*)d_in[0];
    float4*       y = (float4*)d_out;

    static int nsm = 0;
    if (nsm == 0) {
        cudaDeviceProp prop;
        cudaGetDeviceProperties(&prop, 0);
        nsm = prop.multiProcessorCount;               // 152 on GB300
    }
    const int G = 2 * nsm;                            // even waves for phase A

    // B: 64 MB / (256 threads * 4 float4 * 16 B) = 4096 blocks per slab
    const unsigned bBlocks = (NROWS / 4) * SLABC4 / 256;  // 4096

    for (int slab = 0; slab < NSLABS; ++slab) {
        reduceA_kernel<<<G, 512>>>(x, slab, G);
        scaleB_kernel<<<bBlocks, 256>>>(x, y, slab);
    }
}